// round 1
// baseline (speedup 1.0000x reference)
#include <cuda_runtime.h>

#define B_ 2048
#define S_ 64
#define D_ 512
#define N_ 64
#define A_ 64
#define F_ 512
#define PAD_F 516   // padded row stride (floats) for the big 64x512 SMEM buffer

// ---------------- persistent device scratch (no allocations allowed) ----------
__device__ float g_WvT[F_ * F_];    // [g][f]  = Wv[f][g]
__device__ float g_WaeT[A_ * F_];   // [alpha][f] = W_ae[f][alpha]
__device__ float g_ident[N_ * F_];  // ident[n][f] = W_ie[f][n] + b_ie[f]
__device__ float g_k[N_ * F_];      // k[n][g] = sum_f ident[n][f] * Wk[g][f]
__device__ float g_kq[N_ * D_];     // kq[n][d] = scale * sum_f k[n][f] * Wq[f][d]

// ---------------- setup 1: transposes + identity encoder ----------------------
__global__ void setup_transpose(const float* __restrict__ Wv,
                                const float* __restrict__ W_ae,
                                const float* __restrict__ W_ie,
                                const float* __restrict__ b_ie) {
    int t = blockIdx.x * blockDim.x + threadIdx.x;
    int stride = gridDim.x * blockDim.x;
    for (int i = t; i < F_ * F_; i += stride) {
        int g = i >> 9, f = i & 511;
        g_WvT[i] = Wv[f * F_ + g];
    }
    for (int i = t; i < A_ * F_; i += stride) {
        int al = i >> 9, f = i & 511;
        g_WaeT[i] = W_ae[f * A_ + al];
    }
    for (int i = t; i < N_ * F_; i += stride) {
        int n = i >> 9, f = i & 511;
        g_ident[i] = W_ie[f * N_ + n] + b_ie[f];
    }
}

// ---------------- setup 2: k = ident @ Wk^T -----------------------------------
__global__ void setup_k(const float* __restrict__ Wk) {
    int idx = blockIdx.x * blockDim.x + threadIdx.x;  // 32768 outputs
    int n = idx & 63;
    int g = idx >> 6;
    float acc = 0.f;
    for (int f = 0; f < F_; f++)
        acc += g_ident[n * F_ + f] * Wk[g * F_ + f];
    g_k[n * F_ + g] = acc;
}

// ---------------- setup 3: kq = scale * k @ Wq ---------------------------------
__global__ void setup_kq(const float* __restrict__ Wq) {
    int d = threadIdx.x;          // 512 threads: one output column each
    int n0 = blockIdx.x * 8;      // 8 blocks x 8 rows
    float acc[8];
#pragma unroll
    for (int j = 0; j < 8; j++) acc[j] = 0.f;
    for (int f = 0; f < F_; f++) {
        float wq = Wq[f * D_ + d];
#pragma unroll
        for (int j = 0; j < 8; j++)
            acc[j] += g_k[(n0 + j) * F_ + f] * wq;
    }
    const float scale = 0.04419417382415922f;  // 512^-0.5
#pragma unroll
    for (int j = 0; j < 8; j++)
        g_kq[(n0 + j) * D_ + d] = acc[j] * scale;
}

// ---------------- fused main kernel: one block per batch -----------------------
__global__ __launch_bounds__(512, 1)
void abind_main_kernel(const float* __restrict__ slots,
                       const float* __restrict__ actions,
                       const float* __restrict__ b_ae,
                       const float* __restrict__ ln_g,
                       const float* __restrict__ ln_b,
                       float* __restrict__ out_slots,   // [B,S,F]
                       float* __restrict__ out_attn)    // [B,N,S]
{
    extern __shared__ float sm[];
    float* sA    = sm;                    // 64 x PAD_F   (kq -> a_n -> tmp)
    float* sW    = sA + 64 * PAD_F;       // 16 x PAD_F   (WvT chunk; aliases sS)
    float* sS    = sW;                    // 64 x 33      slots chunk (phase L)
    float* sAttn = sW + 16 * PAD_F;       // 64 x 65      logits / attn
    float* sAct  = sAttn + 64 * 65;       // 64 x 65      actions
    float* sMu   = sAct + 64 * 65;        // 64
    float* sRstd = sMu + 64;              // 64

    const int t = threadIdx.x;
    const int b = blockIdx.x;
    const float* slots_b = slots + (size_t)b * S_ * D_;
    const float* act_b   = actions + (size_t)b * N_ * A_;
    float* out1 = out_slots + (size_t)b * S_ * F_;
    float* out2 = out_attn + (size_t)b * N_ * S_;

    // ============ Phase L: logits[n][s] = sum_d kq[n][d] * slots[s][d] ========
#pragma unroll
    for (int j = 0; j < 64; j++)
        sA[j * PAD_F + t] = g_kq[j * 512 + t];
    __syncthreads();

    const int sIdx = t & 15, nIdx = t >> 4;
    const int n0 = nIdx * 2, s0l = sIdx * 4;
    float lacc[2][4];
#pragma unroll
    for (int i = 0; i < 2; i++)
#pragma unroll
        for (int j = 0; j < 4; j++) lacc[i][j] = 0.f;

    for (int kc = 0; kc < 16; kc++) {
#pragma unroll
        for (int j = 0; j < 4; j++) {
            int i = t + j * 512;
            int s = i >> 5, d = i & 31;
            sS[s * 33 + d] = slots_b[s * 512 + kc * 32 + d];
        }
        __syncthreads();
#pragma unroll
        for (int d = 0; d < 32; d++) {
            float a0 = sA[n0 * PAD_F + kc * 32 + d];
            float a1 = sA[(n0 + 1) * PAD_F + kc * 32 + d];
            float b0 = sS[(s0l + 0) * 33 + d];
            float b1 = sS[(s0l + 1) * 33 + d];
            float b2 = sS[(s0l + 2) * 33 + d];
            float b3 = sS[(s0l + 3) * 33 + d];
            lacc[0][0] += a0 * b0; lacc[0][1] += a0 * b1;
            lacc[0][2] += a0 * b2; lacc[0][3] += a0 * b3;
            lacc[1][0] += a1 * b0; lacc[1][1] += a1 * b1;
            lacc[1][2] += a1 * b2; lacc[1][3] += a1 * b3;
        }
        __syncthreads();
    }
#pragma unroll
    for (int i = 0; i < 2; i++)
#pragma unroll
        for (int j = 0; j < 4; j++)
            sAttn[(n0 + i) * 65 + s0l + j] = lacc[i][j];
    __syncthreads();

    // ============ softmax over s (row n), write attn out, add EPS =============
    if (t < 64) {
        float m = -3.4e38f;
#pragma unroll
        for (int s = 0; s < 64; s++) m = fmaxf(m, sAttn[t * 65 + s]);
        float sum = 0.f;
#pragma unroll
        for (int s = 0; s < 64; s++) {
            float e = __expf(sAttn[t * 65 + s] - m);
            sAttn[t * 65 + s] = e;
            sum += e;
        }
        float inv = 1.f / sum;
#pragma unroll
        for (int s = 0; s < 64; s++) sAttn[t * 65 + s] *= inv;
    }
    __syncthreads();
#pragma unroll
    for (int j = 0; j < 8; j++) {
        int i = t + j * 512;
        int n = i >> 6, s = i & 63;
        float v = sAttn[n * 65 + s];
        out2[i] = v;                      // attn output (no eps)
        sAttn[n * 65 + s] = v + 1e-8f;    // eps-shifted for weighting
    }

    // ============ Phase A: a = actions @ W_ae^T + b_ae; LayerNorm -> a_n ======
#pragma unroll
    for (int j = 0; j < 8; j++) {
        int i = t + j * 512;
        sAct[(i >> 6) * 65 + (i & 63)] = act_b[i];
    }
    __syncthreads();
    {
        float acc[64];
#pragma unroll
        for (int n = 0; n < 64; n++) acc[n] = 0.f;
        for (int al = 0; al < 64; al++) {
            float w = g_WaeT[al * 512 + t];
#pragma unroll
            for (int n = 0; n < 64; n++)
                acc[n] += sAct[n * 65 + al] * w;
        }
        float bias = b_ae[t];
#pragma unroll
        for (int n = 0; n < 64; n++)
            sA[n * PAD_F + t] = acc[n] + bias;
    }
    __syncthreads();
    {   // LN stats: warp w handles rows 4w..4w+3; two-pass for accuracy
        int w = t >> 5, lane = t & 31;
#pragma unroll
        for (int r0 = 0; r0 < 4; r0++) {
            int row = w * 4 + r0;
            float s = 0.f;
#pragma unroll
            for (int j = 0; j < 16; j++) s += sA[row * PAD_F + lane + 32 * j];
#pragma unroll
            for (int o = 16; o > 0; o >>= 1) s += __shfl_xor_sync(0xffffffffu, s, o);
            float mu = s * (1.f / 512.f);
            float vs = 0.f;
#pragma unroll
            for (int j = 0; j < 16; j++) {
                float dv = sA[row * PAD_F + lane + 32 * j] - mu;
                vs += dv * dv;
            }
#pragma unroll
            for (int o = 16; o > 0; o >>= 1) vs += __shfl_xor_sync(0xffffffffu, vs, o);
            if (lane == 0) {
                sMu[row] = mu;
                sRstd[row] = rsqrtf(vs * (1.f / 512.f) + 1e-5f);
            }
        }
    }
    __syncthreads();
    {
        float g = ln_g[t], bb = ln_b[t];
#pragma unroll
        for (int r = 0; r < 64; r++)
            sA[r * PAD_F + t] = (sA[r * PAD_F + t] - sMu[r]) * sRstd[r] * g + bb;
    }
    __syncthreads();

    // ============ Phase T: tmp[s][f] = sum_n (attn[n][s]+eps) * a_n[n][f] =====
    // column-private in-place transform of sA (thread t owns column f = t)
    {
        float acc[64];
#pragma unroll
        for (int s = 0; s < 64; s++) acc[s] = 0.f;
        for (int n = 0; n < 64; n++) {
            float a = sA[n * PAD_F + t];
#pragma unroll
            for (int s = 0; s < 64; s++)
                acc[s] += sAttn[n * 65 + s] * a;
        }
#pragma unroll
        for (int s = 0; s < 64; s++) sA[s * PAD_F + t] = acc[s];
    }
    __syncthreads();

    // ============ Phase O: out[s][f] = sum_g tmp[s][g] * WvT[g][f] ============
    {
        const int f0 = (t & 127) * 4;   // 4 contiguous f per thread (float4)
        const int s0 = (t >> 7) * 16;   // 16 s-rows per thread
        float acc[16][4];
#pragma unroll
        for (int i = 0; i < 16; i++)
#pragma unroll
            for (int j = 0; j < 4; j++) acc[i][j] = 0.f;

        for (int gc = 0; gc < 32; gc++) {
            __syncthreads();
#pragma unroll
            for (int j = 0; j < 16; j++)
                sW[j * PAD_F + t] = g_WvT[(gc * 16 + j) * 512 + t];
            __syncthreads();
#pragma unroll
            for (int g = 0; g < 16; g++) {
                float4 wv = *reinterpret_cast<const float4*>(&sW[g * PAD_F + f0]);
                float ts[16];
#pragma unroll
                for (int i = 0; i < 16; i++)
                    ts[i] = sA[(s0 + i) * PAD_F + gc * 16 + g];
#pragma unroll
                for (int i = 0; i < 16; i++) {
                    acc[i][0] += ts[i] * wv.x;
                    acc[i][1] += ts[i] * wv.y;
                    acc[i][2] += ts[i] * wv.z;
                    acc[i][3] += ts[i] * wv.w;
                }
            }
        }
#pragma unroll
        for (int i = 0; i < 16; i++) {
            float4 o = make_float4(acc[i][0], acc[i][1], acc[i][2], acc[i][3]);
            *reinterpret_cast<float4*>(&out1[(s0 + i) * 512 + f0]) = o;
        }
    }
}

// ---------------- launch ------------------------------------------------------
extern "C" void kernel_launch(void* const* d_in, const int* in_sizes, int n_in,
                              void* d_out, int out_size) {
    const float* slots   = (const float*)d_in[0];
    const float* actions = (const float*)d_in[1];
    const float* W_ae    = (const float*)d_in[2];
    const float* b_ae    = (const float*)d_in[3];
    const float* W_ie    = (const float*)d_in[4];
    const float* b_ie    = (const float*)d_in[5];
    const float* ln_g    = (const float*)d_in[6];
    const float* ln_b    = (const float*)d_in[7];
    const float* Wq      = (const float*)d_in[8];
    const float* Wk      = (const float*)d_in[9];
    const float* Wv      = (const float*)d_in[10];

    float* out      = (float*)d_out;
    float* out_attn = out + (size_t)B_ * S_ * F_;

    setup_transpose<<<256, 256>>>(Wv, W_ae, W_ie, b_ie);
    setup_k<<<128, 256>>>(Wk);
    setup_kq<<<8, 512>>>(Wq);

    const size_t SMEM =
        (64 * PAD_F + 16 * PAD_F + 64 * 65 + 64 * 65 + 128) * sizeof(float);
    cudaFuncSetAttribute(abind_main_kernel,
                         cudaFuncAttributeMaxDynamicSharedMemorySize, (int)SMEM);
    abind_main_kernel<<<B_, 512, SMEM>>>(slots, actions, b_ae, ln_g, ln_b,
                                         out, out_attn);
}

// round 3
// speedup vs baseline: 1.7066x; 1.7066x over previous
#include <cuda_runtime.h>
#include <cstdint>

#define B_ 2048
#define S_ 64
#define D_ 512
#define N_ 64
#define A_ 64
#define F_ 512
#define PAD_F 516

// ---------------- persistent device scratch ------------------------------------
__device__ float g_WvT[F_ * F_];    // WvT[f][g] = Wv[g][f]
__device__ float g_ident[N_ * F_];  // W_ie[f][n] + b_ie[f]
__device__ float g_k[N_ * F_];
__device__ float g_kq[N_ * D_];     // scale * k @ Wq
__device__ float g_M1[A_ * F_];     // M1[al][go] = sum_f W_ae[f,al] g[f] Wv[go,f]
__device__ float g_c1[F_];          // sum_f b_ae[f] g[f] Wv[go,f]
__device__ float g_c2[F_];          // sum_f g[f] Wv[go,f]
__device__ float g_c3[F_];          // sum_f ln_b[f] Wv[go,f]
__device__ float g_G2[A_ * A_];     // W_ae^T W_ae
__device__ float g_wb[A_];          // sum_f W_ae[f,al] b_ae[f]
__device__ float g_wsum[A_];        // sum_f W_ae[f,al]
__device__ float g_scal[2];         // [0]=sum b_ae^2, [1]=sum b_ae

// ---------------- setup 1: Wv transpose + identity encoder ---------------------
__global__ void setup_transpose(const float* __restrict__ Wv,
                                const float* __restrict__ W_ie,
                                const float* __restrict__ b_ie) {
    int t = blockIdx.x * blockDim.x + threadIdx.x;
    int stride = gridDim.x * blockDim.x;
    for (int i = t; i < F_ * F_; i += stride) {
        int g = i >> 9, f = i & 511;
        g_WvT[i] = Wv[f * F_ + g];      // g_WvT[(g,f)] laid out [g][f]? -> see below
    }
    for (int i = t; i < N_ * F_; i += stride) {
        int n = i >> 9, f = i & 511;
        g_ident[i] = W_ie[f * N_ + n] + b_ie[f];
    }
}
// NOTE: with i=(g,f): g_WvT[g*512+f] = Wv[f*512+g], i.e. g_WvT[x][y] = Wv[y][x].
// So g_WvT[f*512+go] = Wv[go*512+f] = Wv[go,f]  -> exactly what setup_M1 needs.

// ---------------- setup 2: k = ident @ Wk^T ------------------------------------
__global__ void setup_k(const float* __restrict__ Wk) {
    int idx = blockIdx.x * blockDim.x + threadIdx.x;
    int n = idx & 63;
    int g = idx >> 6;
    float acc = 0.f;
    for (int f = 0; f < F_; f++)
        acc += g_ident[n * F_ + f] * Wk[g * F_ + f];
    g_k[n * F_ + g] = acc;
}

// ---------------- setup 3: kq = scale * k @ Wq ----------------------------------
__global__ void setup_kq(const float* __restrict__ Wq) {
    int d = threadIdx.x;
    int n0 = blockIdx.x * 8;
    float acc[8];
#pragma unroll
    for (int j = 0; j < 8; j++) acc[j] = 0.f;
    for (int f = 0; f < F_; f++) {
        float wq = Wq[f * D_ + d];
#pragma unroll
        for (int j = 0; j < 8; j++)
            acc[j] += g_k[(n0 + j) * F_ + f] * wq;
    }
    const float scale = 0.04419417382415922f;  // 512^-0.5
#pragma unroll
    for (int j = 0; j < 8; j++)
        g_kq[(n0 + j) * D_ + d] = acc[j] * scale;
}

// ---------------- setup 4: M1, c1, c2, c3 (uses g_WvT, coalesced) ---------------
__global__ void setup_M1(const float* __restrict__ W_ae,
                         const float* __restrict__ b_ae,
                         const float* __restrict__ ln_g,
                         const float* __restrict__ ln_b) {
    int t = threadIdx.x;           // go = t
    int b = blockIdx.x;            // 0..63 -> M1 row alpha; 64,65,66 -> c1,c2,c3
    float acc = 0.f;
    if (b < 64) {
        for (int f = 0; f < F_; f++)
            acc += W_ae[f * A_ + b] * ln_g[f] * g_WvT[f * 512 + t];
        g_M1[b * 512 + t] = acc;
    } else if (b == 64) {
        for (int f = 0; f < F_; f++)
            acc += b_ae[f] * ln_g[f] * g_WvT[f * 512 + t];
        g_c1[t] = acc;
    } else if (b == 65) {
        for (int f = 0; f < F_; f++)
            acc += ln_g[f] * g_WvT[f * 512 + t];
        g_c2[t] = acc;
    } else {
        for (int f = 0; f < F_; f++)
            acc += ln_b[f] * g_WvT[f * 512 + t];
        g_c3[t] = acc;
    }
}

// ---------------- setup 5: G2, wb, wsum, scalars ---------------------------------
__global__ void setup_G2(const float* __restrict__ W_ae,
                         const float* __restrict__ b_ae) {
    int idx = blockIdx.x * blockDim.x + threadIdx.x;
    if (blockIdx.x < 8) {
        int al = idx & 63, be = idx >> 6;
        float acc = 0.f;
        for (int f = 0; f < F_; f++)
            acc += W_ae[f * A_ + al] * W_ae[f * A_ + be];
        g_G2[al * A_ + be] = acc;
    } else {
        int t = threadIdx.x;
        if (t < 64) {
            float aw = 0.f, as = 0.f;
            for (int f = 0; f < F_; f++) {
                float w = W_ae[f * A_ + t];
                aw += w * b_ae[f];
                as += w;
            }
            g_wb[t] = aw;
            g_wsum[t] = as;
        } else if (t == 64) {
            float bb = 0.f, sb = 0.f;
            for (int f = 0; f < F_; f++) {
                float v = b_ae[f];
                bb += v * v;
                sb += v;
            }
            g_scal[0] = bb;
            g_scal[1] = sb;
        }
    }
}

// ---------------- fused main kernel: one block per batch ------------------------
__global__ __launch_bounds__(512, 1)
void abind_main_kernel(const float* __restrict__ slots,
                       const float* __restrict__ actions,
                       float* __restrict__ out_slots,   // [B,S,F]
                       float* __restrict__ out_attn)    // [B,N,S]
{
    extern __shared__ float sm[];
    float* sA    = sm;                    // 64 x PAD_F   (kq -> P -> v)
    float* sS    = sA + 64 * PAD_F;       // 64 x 33      slots chunk
    float* sAttn = sS + 64 * 33;          // 64 x 65      logits / attn(+eps)
    float* sAct  = sAttn + 64 * 65;       // 64 x 65      actions
    float* sG2   = sAct + 64 * 65;        // 64 x 65
    float* sWb   = sG2 + 64 * 65;         // 64
    float* sWsum = sWb + 64;              // 64
    float* sMu   = sWsum + 64;            // 64
    float* sRstd = sMu + 64;              // 64

    const int t = threadIdx.x;
    const int b = blockIdx.x;
    const float* slots_b = slots + (size_t)b * S_ * D_;
    const float* act_b   = actions + (size_t)b * N_ * A_;
    float* out1 = out_slots + (size_t)b * S_ * F_;
    float* out2 = out_attn + (size_t)b * N_ * S_;

    // ============ Phase L: logits[n][s] = sum_d kq[n][d] * slots[s][d] ========
#pragma unroll
    for (int j = 0; j < 64; j++)
        sA[j * PAD_F + t] = g_kq[j * 512 + t];
    // also stage the stats tables while we're at it (separate smem, no conflict)
    {
#pragma unroll
        for (int j = 0; j < 8; j++) {
            int i = t + j * 512;       // 4096 G2 entries
            sG2[(i >> 6) * 65 + (i & 63)] = g_G2[i];
        }
        if (t < 64) { sWb[t] = g_wb[t]; sWsum[t] = g_wsum[t]; }
    }
    __syncthreads();

    const int sIdx = t & 15, nIdx = t >> 4;
    const int n0 = nIdx * 2, s0l = sIdx * 4;
    float lacc[2][4];
#pragma unroll
    for (int i = 0; i < 2; i++)
#pragma unroll
        for (int j = 0; j < 4; j++) lacc[i][j] = 0.f;

    for (int kc = 0; kc < 16; kc++) {
#pragma unroll
        for (int j = 0; j < 4; j++) {
            int i = t + j * 512;
            int s = i >> 5, d = i & 31;
            sS[s * 33 + d] = slots_b[s * 512 + kc * 32 + d];
        }
        __syncthreads();
#pragma unroll
        for (int d = 0; d < 32; d++) {
            float a0 = sA[n0 * PAD_F + kc * 32 + d];
            float a1 = sA[(n0 + 1) * PAD_F + kc * 32 + d];
            float b0 = sS[(s0l + 0) * 33 + d];
            float b1 = sS[(s0l + 1) * 33 + d];
            float b2 = sS[(s0l + 2) * 33 + d];
            float b3 = sS[(s0l + 3) * 33 + d];
            lacc[0][0] += a0 * b0; lacc[0][1] += a0 * b1;
            lacc[0][2] += a0 * b2; lacc[0][3] += a0 * b3;
            lacc[1][0] += a1 * b0; lacc[1][1] += a1 * b1;
            lacc[1][2] += a1 * b2; lacc[1][3] += a1 * b3;
        }
        __syncthreads();
    }
#pragma unroll
    for (int i = 0; i < 2; i++)
#pragma unroll
        for (int j = 0; j < 4; j++)
            sAttn[(n0 + i) * 65 + s0l + j] = lacc[i][j];
    __syncthreads();

    // ============ softmax over s (row n), write attn out, add EPS =============
    if (t < 64) {
        float m = -3.4e38f;
#pragma unroll
        for (int s = 0; s < 64; s++) m = fmaxf(m, sAttn[t * 65 + s]);
        float sum = 0.f;
#pragma unroll
        for (int s = 0; s < 64; s++) {
            float e = __expf(sAttn[t * 65 + s] - m);
            sAttn[t * 65 + s] = e;
            sum += e;
        }
        float inv = 1.f / sum;
#pragma unroll
        for (int s = 0; s < 64; s++) sAttn[t * 65 + s] *= inv;
    }
    __syncthreads();
#pragma unroll
    for (int j = 0; j < 8; j++) {
        int i = t + j * 512;
        int n = i >> 6, s = i & 63;
        float v = sAttn[n * 65 + s];
        out2[i] = v;
        sAttn[n * 65 + s] = v + 1e-8f;
    }

    // ============ Phase P: P[n][t] = sum_al actions[n][al]*M1[al][t] + c1[t] ==
#pragma unroll
    for (int j = 0; j < 8; j++) {
        int i = t + j * 512;
        sAct[(i >> 6) * 65 + (i & 63)] = act_b[i];
    }
    __syncthreads();
    {
        float acc[64];
#pragma unroll
        for (int n = 0; n < 64; n++) acc[n] = 0.f;
        for (int al = 0; al < 64; al++) {
            float w = g_M1[al * 512 + t];
#pragma unroll
            for (int n = 0; n < 64; n++)
                acc[n] += sAct[n * 65 + al] * w;
        }
        float c1t = g_c1[t];
#pragma unroll
        for (int n = 0; n < 64; n++)
            sA[n * PAD_F + t] = acc[n] + c1t;
    }

    // ============ Stats: mu_n, rstd_n from closed forms =======================
    // thread t: n = t>>3, seg = t&7 ; each handles 8 beta columns
    {
        const int n = t >> 3, seg = t & 7;
        float dotj[8];
#pragma unroll
        for (int j = 0; j < 8; j++) dotj[j] = 0.f;
        for (int al = 0; al < 64; al++) {
            float av = sAct[n * 65 + al];
#pragma unroll
            for (int j = 0; j < 8; j++)
                dotj[j] += av * sG2[al * 65 + seg * 8 + j];
        }
        float quad = 0.f, wbp = 0.f, wsp = 0.f;
#pragma unroll
        for (int j = 0; j < 8; j++) {
            int be = seg * 8 + j;
            float ab = sAct[n * 65 + be];
            quad += ab * dotj[j];
            wbp  += ab * sWb[be];
            wsp  += ab * sWsum[be];
        }
#pragma unroll
        for (int o = 1; o < 8; o <<= 1) {
            quad += __shfl_xor_sync(0xffffffffu, quad, o);
            wbp  += __shfl_xor_sync(0xffffffffu, wbp, o);
            wsp  += __shfl_xor_sync(0xffffffffu, wsp, o);
        }
        if (seg == 0) {
            float bb = g_scal[0], sb = g_scal[1];
            float mu = (wsp + sb) * (1.f / 512.f);
            float e2 = (quad + 2.f * wbp + bb) * (1.f / 512.f);
            float var = e2 - mu * mu;
            sMu[n] = mu;
            sRstd[n] = rsqrtf(var + 1e-5f);
        }
    }
    __syncthreads();

    // ============ v[n][t] = rstd*P - rstd*mu*c2[t] + c3[t] ====================
    {
        float c2t = g_c2[t], c3t = g_c3[t];
#pragma unroll
        for (int r = 0; r < 64; r++) {
            float rs = sRstd[r];
            float base = fmaf(-rs * sMu[r], c2t, c3t);
            sA[r * PAD_F + t] = fmaf(rs, sA[r * PAD_F + t], base);
        }
    }
    __syncthreads();

    // ============ Phase T: out[s][t] = sum_n (attn[n][s]+eps) * v[n][t] ======
    {
        float acc[64];
#pragma unroll
        for (int s = 0; s < 64; s++) acc[s] = 0.f;
        for (int n = 0; n < 64; n++) {
            float a = sA[n * PAD_F + t];
#pragma unroll
            for (int s = 0; s < 64; s++)
                acc[s] += sAttn[n * 65 + s] * a;
        }
#pragma unroll
        for (int s = 0; s < 64; s++)
            out1[s * 512 + t] = acc[s];
    }
}

// ---------------- launch --------------------------------------------------------
extern "C" void kernel_launch(void* const* d_in, const int* in_sizes, int n_in,
                              void* d_out, int out_size) {
    const float* slots   = (const float*)d_in[0];
    const float* actions = (const float*)d_in[1];
    const float* W_ae    = (const float*)d_in[2];
    const float* b_ae    = (const float*)d_in[3];
    const float* W_ie    = (const float*)d_in[4];
    const float* b_ie    = (const float*)d_in[5];
    const float* ln_g    = (const float*)d_in[6];
    const float* ln_b    = (const float*)d_in[7];
    const float* Wq      = (const float*)d_in[8];
    const float* Wk      = (const float*)d_in[9];
    const float* Wv      = (const float*)d_in[10];

    float* out      = (float*)d_out;
    float* out_attn = out + (size_t)B_ * S_ * F_;

    setup_transpose<<<256, 256>>>(Wv, W_ie, b_ie);
    setup_k<<<128, 256>>>(Wk);
    setup_kq<<<8, 512>>>(Wq);
    setup_M1<<<67, 512>>>(W_ae, b_ae, ln_g, ln_b);
    setup_G2<<<9, 512>>>(W_ae, b_ae);

    const size_t SMEM =
        (64 * PAD_F + 64 * 33 + 64 * 65 * 3 + 4 * 64) * sizeof(float);
    cudaFuncSetAttribute(abind_main_kernel,
                         cudaFuncAttributeMaxDynamicSharedMemorySize, (int)SMEM);
    abind_main_kernel<<<B_, 512, SMEM>>>(slots, actions, out, out_attn);
}